// round 14
// baseline (speedup 1.0000x reference)
#include <cuda_runtime.h>
#include <cstdint>

#define BB 16
#define NN 2048
#define CC 256
#define RR 128
#define KK 16

// ---------------- static device scratch ----------------
__device__ float g_xpre[BB * RR * NN];   // mlp1 pre-BN, channel-major
__device__ int   g_idx[BB * NN * KK];    // top-16 neighbor indices
__device__ float g_y[BB * NN * RR];      // fc(relu(bn1(xpre))), point-major
__device__ float g_x2c[BB * RR * NN];    // group-max output, channel-major
__device__ float g_lapc[BB * RR * NN];   // laplacian, channel-major
__device__ float g_t[BB * RR * NN];      // lu output pre-BN, channel-major
__device__ float g_y2[BB * CC * NN];     // mlp2 pre-BN, channel-major
__device__ float g_y3[BB * 2 * CC * NN]; // mlp3 pre-BN, channel-major
__device__ int   g_cnt[BB * NN];         // gather histogram for BNg
__device__ float g_stat[2304];           // per-BN sums / sumsqs
__device__ float g_aff[2304];            // per-BN scale / shift

__device__ __forceinline__ float tf32r(float x) {
    float o;
    asm("cvt.rna.tf32.f32 %0, %1;" : "=f"(o) : "f"(x));
    return o;
}

// ---------------- zero accumulators ----------------
__global__ void k_zero() {
    int i = blockIdx.x * 256 + threadIdx.x;
    if (i < BB * NN) g_cnt[i] = 0;
    if (i < 2304)    g_stat[i] = 0.f;
}

// ---------------- kNN top-16 on 2D coords (exact fp32, XLA association) ----------------
__global__ void k_knn(const float* __restrict__ xyz) {
    __shared__ float sx[NN];
    __shared__ float sy[NN];
    __shared__ float sxx[NN];
    int b = blockIdx.y;
    const float* px = xyz + (size_t)b * 3 * NN;
    for (int i = threadIdx.x; i < NN; i += 256) {
        float xv = px[i], yv = px[NN + i];
        sx[i] = xv; sy[i] = yv;
        sxx[i] = __fadd_rn(__fmul_rn(xv, xv), __fmul_rn(yv, yv));
    }
    __syncthreads();
    int n = blockIdx.x * 256 + threadIdx.x;
    float qx = sx[n], qy = sy[n], qxx = sxx[n];
    float bd[KK];
    int   bi[KK];
#pragma unroll
    for (int j = 0; j < KK; j++) { bd[j] = 3.4e38f; bi[j] = 0; }
    for (int m = 0; m < NN; m++) {
        float inner = __fmaf_rn(qy, sy[m], __fmul_rn(qx, sx[m]));
        float d = __fadd_rn(__fsub_rn(qxx, 2.f * inner), sxx[m]);
        if (d < bd[KK - 1]) {
            bd[KK - 1] = d; bi[KK - 1] = m;
#pragma unroll
            for (int j = KK - 1; j >= 1; j--) {
                if (bd[j] < bd[j - 1]) {
                    float td = bd[j]; bd[j] = bd[j - 1]; bd[j - 1] = td;
                    int   ti = bi[j]; bi[j] = bi[j - 1]; bi[j - 1] = ti;
                }
            }
        }
    }
    int* op = g_idx + ((size_t)b * NN + n) * KK;
#pragma unroll
    for (int j = 0; j < KK; j++) op[j] = bi[j];
}

// ---------------- histogram of first-8 neighbor indices ----------------
__global__ void k_cnt() {
    int b = blockIdx.x;
    for (int row = threadIdx.x; row < NN; row += blockDim.x) {
        const int* p = g_idx + ((size_t)b * NN + row) * KK;
#pragma unroll
        for (int j = 0; j < 8; j++) atomicAdd(&g_cnt[b * NN + p[j]], 1);
    }
}

// ---------------- tf32 mma.sync GEMM: out = W @ f(in) + bias (channel-major) ----
// MODE 0: raw input. MODE 2: relu(in*scale+shift) + add.
// Block tile 128x128, 8 warps (4M x 2N), warp tile 32x64 of m16n8k8 frags.
// offS >= 0: fused BN stats.
#define AST 36
#define BST 33
template <int MODE>
__global__ void __launch_bounds__(256)
k_tmma(const float* __restrict__ W, const float* __restrict__ in,
       const float* __restrict__ bias,
       const float* __restrict__ scale, const float* __restrict__ shift,
       const float* __restrict__ add,
       float* __restrict__ out, int M, int Kd, int offS) {
    __shared__ float As[128 * AST];   // W tile [m][k], tf32-rounded
    __shared__ float Bs[128 * BST];   // in tile [n][k], tf32-rounded
    int tid = threadIdx.x, wid = tid >> 5, lane = tid & 31;
    int gid = lane >> 2, tig = lane & 3;
    int b = blockIdx.z, n0 = blockIdx.x * 128, m0 = blockIdx.y * 128;
    int mw = wid >> 1, nw = wid & 1;           // warp grid 4M x 2N
    const float* inb = in + (size_t)b * Kd * NN;
    const float* addb = (MODE == 2) ? add + (size_t)b * Kd * NN : in;

    float c[2][8][4];
#pragma unroll
    for (int i = 0; i < 2; i++)
#pragma unroll
        for (int j = 0; j < 8; j++)
#pragma unroll
            for (int q = 0; q < 4; q++) c[i][j][q] = 0.f;

    int nch = Kd >> 5;
    for (int ch = 0; ch < nch; ch++) {
        // stage W chunk: [128 m][32 k], row-coalesced global reads
        for (int e = tid; e < 128 * 32; e += 256) {
            int m = e >> 5, k = e & 31;
            As[m * AST + k] = tf32r(W[(size_t)(m0 + m) * Kd + ch * 32 + k]);
        }
        // stage input chunk transposed: [128 n][32 k], n-coalesced global reads
        for (int e = tid; e < 128 * 32; e += 256) {
            int n = e & 127, k = e >> 7;
            int kg = ch * 32 + k;
            float v = inb[(size_t)kg * NN + n0 + n];
            if (MODE >= 1) v = fmaxf(fmaf(v, scale[kg], shift[kg]), 0.f);
            if (MODE == 2) v += addb[(size_t)kg * NN + n0 + n];
            Bs[n * BST + k] = tf32r(v);
        }
        __syncthreads();
#pragma unroll
        for (int ks = 0; ks < 4; ks++) {
            int kb = ks * 8;
            uint32_t a[2][4];
#pragma unroll
            for (int i = 0; i < 2; i++) {
                int r = mw * 32 + i * 16 + gid;
                a[i][0] = __float_as_uint(As[r * AST + kb + tig]);
                a[i][1] = __float_as_uint(As[(r + 8) * AST + kb + tig]);
                a[i][2] = __float_as_uint(As[r * AST + kb + tig + 4]);
                a[i][3] = __float_as_uint(As[(r + 8) * AST + kb + tig + 4]);
            }
#pragma unroll
            for (int j = 0; j < 8; j++) {
                int n = nw * 64 + j * 8 + gid;
                uint32_t b0 = __float_as_uint(Bs[n * BST + kb + tig]);
                uint32_t b1 = __float_as_uint(Bs[n * BST + kb + tig + 4]);
#pragma unroll
                for (int i = 0; i < 2; i++) {
                    asm volatile(
                        "mma.sync.aligned.m16n8k8.row.col.f32.tf32.tf32.f32 "
                        "{%0,%1,%2,%3}, {%4,%5,%6,%7}, {%8,%9}, {%0,%1,%2,%3};"
                        : "+f"(c[i][j][0]), "+f"(c[i][j][1]),
                          "+f"(c[i][j][2]), "+f"(c[i][j][3])
                        : "r"(a[i][0]), "r"(a[i][1]), "r"(a[i][2]), "r"(a[i][3]),
                          "r"(b0), "r"(b1));
                }
            }
        }
        __syncthreads();
    }

    // epilogue: bias, fused BN stats, float2 stores (one 32B sector per quad)
    float sA[2][2] = {{0.f, 0.f}, {0.f, 0.f}};
    float qA[2][2] = {{0.f, 0.f}, {0.f, 0.f}};
#pragma unroll
    for (int i = 0; i < 2; i++) {
#pragma unroll
        for (int h = 0; h < 2; h++) {
            int row = m0 + mw * 32 + i * 16 + gid + h * 8;
            float bv = bias[row];
            float* orow = out + ((size_t)b * M + row) * NN + n0 + nw * 64;
#pragma unroll
            for (int j = 0; j < 8; j++) {
                float v0 = c[i][j][h * 2] + bv;
                float v1 = c[i][j][h * 2 + 1] + bv;
                sA[i][h] += v0 + v1;
                qA[i][h] += v0 * v0 + v1 * v1;
                *reinterpret_cast<float2*>(&orow[j * 8 + tig * 2]) = make_float2(v0, v1);
            }
        }
    }
    if (offS >= 0) {
#pragma unroll
        for (int i = 0; i < 2; i++)
#pragma unroll
            for (int h = 0; h < 2; h++) {
                float s = sA[i][h], q = qA[i][h];
                s += __shfl_xor_sync(0xffffffffu, s, 1);
                q += __shfl_xor_sync(0xffffffffu, q, 1);
                s += __shfl_xor_sync(0xffffffffu, s, 2);
                q += __shfl_xor_sync(0xffffffffu, q, 2);
                if (tig == 0) {
                    int row = m0 + mw * 32 + i * 16 + gid + h * 8;
                    atomicAdd(&g_stat[offS + row], s);
                    atomicAdd(&g_stat[offS + M + row], q);
                }
            }
    }
}

// ---------------- SIMT GEMM for fc (point-major out, fused weighted BNg stats) ----
__global__ void k_gemm_fc(const float* __restrict__ W, const float* __restrict__ in,
                          const float* __restrict__ bias,
                          const float* __restrict__ scale, const float* __restrict__ shift,
                          float* __restrict__ out) {
    const int M = RR, Kd = RR;
    __shared__ __align__(16) float Ws[16][68];
    __shared__ __align__(16) float Xs[16][68];
    int b = blockIdx.z;
    int n0 = blockIdx.x * 64, m0 = blockIdx.y * 64;
    int tid = threadIdx.x;
    int tx = tid & 15, ty = tid >> 4;
    const float* inb = in + (size_t)b * Kd * NN;
    float acc[4][4];
#pragma unroll
    for (int i = 0; i < 4; i++)
#pragma unroll
        for (int j = 0; j < 4; j++) acc[i][j] = 0.f;

    for (int k0 = 0; k0 < Kd; k0 += 16) {
        int kw = tid & 15, mw = tid >> 4;
#pragma unroll
        for (int p = 0; p < 4; p++)
            Ws[kw][mw + p * 16] = tf32r(W[(size_t)(m0 + mw + p * 16) * Kd + k0 + kw]);
        int nn2 = tid & 63, kk = tid >> 6;
#pragma unroll
        for (int p = 0; p < 4; p++) {
            int kg = k0 + kk + p * 4;
            float v = inb[(size_t)kg * NN + n0 + nn2];
            v = fmaxf(fmaf(v, scale[kg], shift[kg]), 0.f);
            Xs[kk + p * 4][nn2] = tf32r(v);
        }
        __syncthreads();
#pragma unroll
        for (int kk2 = 0; kk2 < 16; kk2++) {
            float4 xv = *reinterpret_cast<const float4*>(&Xs[kk2][tx * 4]);
            float4 wv = *reinterpret_cast<const float4*>(&Ws[kk2][ty * 4]);
            float xa[4] = {xv.x, xv.y, xv.z, xv.w};
            float wa[4] = {wv.x, wv.y, wv.z, wv.w};
#pragma unroll
            for (int i = 0; i < 4; i++)
#pragma unroll
                for (int j = 0; j < 4; j++)
                    acc[i][j] = fmaf(wa[i], xa[j], acc[i][j]);
        }
        __syncthreads();
    }
    float sW[4] = {0.f, 0.f, 0.f, 0.f}, qW[4] = {0.f, 0.f, 0.f, 0.f};
    int m = m0 + ty * 4;
#pragma unroll
    for (int j = 0; j < 4; j++) {
        int n = n0 + tx * 4 + j;
        float cw = (float)g_cnt[b * NN + n];
        float o0 = acc[0][j] + bias[m],     o1 = acc[1][j] + bias[m + 1];
        float o2 = acc[2][j] + bias[m + 2], o3 = acc[3][j] + bias[m + 3];
        *reinterpret_cast<float4*>(&out[((size_t)b * NN + n) * M + m]) =
            make_float4(o0, o1, o2, o3);
        sW[0] += cw * o0; qW[0] += cw * o0 * o0;
        sW[1] += cw * o1; qW[1] += cw * o1 * o1;
        sW[2] += cw * o2; qW[2] += cw * o2 * o2;
        sW[3] += cw * o3; qW[3] += cw * o3 * o3;
    }
#pragma unroll
    for (int i = 0; i < 4; i++) {
        float s = sW[i], q = qW[i];
#pragma unroll
        for (int off = 1; off < 16; off <<= 1) {
            s += __shfl_xor_sync(0xffffffffu, s, off);
            q += __shfl_xor_sync(0xffffffffu, q, off);
        }
        if (tx == 0) {
            atomicAdd(&g_stat[256 + m + i], s);
            atomicAdd(&g_stat[384 + m + i], q);
        }
    }
}

// ---------------- finalize BN affine ----------------
__global__ void k_fin(const float* __restrict__ gamma, const float* __restrict__ beta,
                      int M, int offS, int offQ, float invcnt) {
    int m = blockIdx.x * 256 + threadIdx.x;
    if (m >= M) return;
    float mu = g_stat[offS + m] * invcnt;
    float var = g_stat[offQ + m] * invcnt - mu * mu;
    float sc = gamma[m] * rsqrtf(var + 1e-5f);
    g_aff[offS + m] = sc;
    g_aff[offQ + m] = beta[m] - mu * sc;
}

// ---------------- group max: x2[b][r][n2] = max_kg relu(bng(y[.,J])) ----------------
__global__ void k_gmax() {
    int n2 = blockIdx.x, b = blockIdx.y;
    __shared__ int sj[8];
    int r = threadIdx.x;
    if (r < 8)
        sj[r] = g_idx[((size_t)b * NN + r * 256 + (n2 >> 3)) * KK + (n2 & 7)];
    __syncthreads();
    float sc = g_aff[256 + r], sh = g_aff[384 + r];
    float u = 0.f;
#pragma unroll
    for (int kg = 0; kg < 8; kg++) {
        float v = g_y[((size_t)b * NN + sj[kg]) * RR + r];
        u = fmaxf(u, fmaxf(fmaf(v, sc, sh), 0.f));
    }
    g_x2c[((size_t)b * RR + r) * NN + n2] = u;
}

// ---------------- laplacian with faithful .view index algebra ----------------
__global__ void k_lap() {
    int n2 = blockIdx.x, b = blockIdx.y;
    int p = n2 >> 4, s = n2 & 15;
    __shared__ float xr[NN];
    __shared__ int si[2048];
    const float* src = g_x2c + ((size_t)b * RR + p) * NN;
    const int* ib = g_idx + ((size_t)b * NN + s * 128) * KK;
    for (int i = threadIdx.x; i < NN; i += 128) { xr[i] = src[i]; si[i] = ib[i]; }
    __syncthreads();
    int r2 = threadIdx.x;
    int u = r2 >> 4, j = r2 & 15;
    float acc = 0.f;
#pragma unroll
    for (int k2 = 0; k2 < 16; k2++)
        acc += xr[si[(k2 * 8 + u) * 16 + j]];
    float own = g_x2c[((size_t)b * RR + r2) * NN + n2];
    g_lapc[((size_t)b * RR + r2) * NN + n2] = own - acc * (1.f / 16.f);
}

// ---------------- final BN3 apply (float4) ----------------
__global__ void k_apply(float* __restrict__ out) {
    int i4 = blockIdx.x * 256 + threadIdx.x;
    int c = (i4 >> 9) & 511;
    float sc = g_aff[1280 + c], sh = g_aff[1792 + c];
    float4 v = reinterpret_cast<const float4*>(g_y3)[i4];
    float4 o;
    o.x = fmaxf(fmaf(v.x, sc, sh), 0.f);
    o.y = fmaxf(fmaf(v.y, sc, sh), 0.f);
    o.z = fmaxf(fmaf(v.z, sc, sh), 0.f);
    o.w = fmaxf(fmaf(v.w, sc, sh), 0.f);
    reinterpret_cast<float4*>(out)[i4] = o;
}

extern "C" void kernel_launch(void* const* d_in, const int* in_sizes, int n_in,
                              void* d_out, int out_size) {
    const float* xyz   = (const float*)d_in[0];
    const float* feat  = (const float*)d_in[1];
    const float* w1    = (const float*)d_in[2];
    const float* b1    = (const float*)d_in[3];
    const float* bn1_g = (const float*)d_in[4];
    const float* bn1_b = (const float*)d_in[5];
    const float* fc_w  = (const float*)d_in[6];
    const float* fc_b  = (const float*)d_in[7];
    const float* bng_g = (const float*)d_in[8];
    const float* bng_b = (const float*)d_in[9];
    const float* lu_w  = (const float*)d_in[10];
    const float* lu_b  = (const float*)d_in[11];
    const float* bnl_g = (const float*)d_in[12];
    const float* bnl_b = (const float*)d_in[13];
    const float* w2    = (const float*)d_in[14];
    const float* b2    = (const float*)d_in[15];
    const float* bn2_g = (const float*)d_in[16];
    const float* bn2_b = (const float*)d_in[17];
    const float* w3    = (const float*)d_in[18];
    const float* b3    = (const float*)d_in[19];
    const float* bn3_g = (const float*)d_in[20];
    const float* bn3_b = (const float*)d_in[21];
    float* out = (float*)d_out;

    float *xpre, *y, *x2c, *lapc, *t, *y2, *y3, *aff;
    cudaGetSymbolAddress((void**)&xpre, g_xpre);
    cudaGetSymbolAddress((void**)&y,    g_y);
    cudaGetSymbolAddress((void**)&x2c,  g_x2c);
    cudaGetSymbolAddress((void**)&lapc, g_lapc);
    cudaGetSymbolAddress((void**)&t,    g_t);
    cudaGetSymbolAddress((void**)&y2,   g_y2);
    cudaGetSymbolAddress((void**)&y3,   g_y3);
    cudaGetSymbolAddress((void**)&aff,  g_aff);

    k_zero<<<128, 256>>>();
    k_knn<<<dim3(8, BB), 256>>>(xyz);
    k_cnt<<<BB, 512>>>();

    // mlp1: xpre = w1 @ feat + b1   (tensor tf32, stats -> 0/128)
    k_tmma<0><<<dim3(16, 1, BB), 256>>>(w1, feat, b1, nullptr, nullptr, nullptr, xpre, RR, CC, 0);
    k_fin<<<1, 256>>>(bn1_g, bn1_b, RR, 0, 128, 1.f / (BB * NN));

    // fc pre-gather (SIMT, point-major out, fused weighted BNg stats -> 256/384)
    k_gemm_fc<<<dim3(32, 2, BB), 256>>>(fc_w, xpre, fc_b, aff, aff + 128, y);
    k_fin<<<1, 256>>>(bng_g, bng_b, RR, 256, 384, 1.f / 262144.f);

    k_gmax<<<dim3(NN, BB), 128>>>();
    k_lap<<<dim3(NN, BB), 128>>>();

    // lu: t = lu_w @ lap + lu_b   (tensor tf32, stats -> 512/640)
    k_tmma<0><<<dim3(16, 1, BB), 256>>>(lu_w, lapc, lu_b, nullptr, nullptr, nullptr, t, RR, RR, 512);
    k_fin<<<1, 256>>>(bnl_g, bnl_b, RR, 512, 640, 1.f / (BB * NN));

    // mlp2: y2 = w2 @ (x2 + relu(bnl(t))) + b2   (tensor tf32, stats -> 768/1024)
    k_tmma<2><<<dim3(16, 2, BB), 256>>>(w2, t, b2, aff + 512, aff + 640, x2c, y2, CC, RR, 768);
    k_fin<<<1, 256>>>(bn2_g, bn2_b, CC, 768, 1024, 1.f / (BB * NN));

    // mlp3: y3 = w3 @ (relu(bn2(y2)) + feat) + b3   (tensor tf32, stats -> 1280/1792)
    k_tmma<2><<<dim3(16, 4, BB), 256>>>(w3, y2, b3, aff + 768, aff + 1024, feat, y3, 2 * CC, CC, 1280);
    k_fin<<<2, 256>>>(bn3_g, bn3_b, 2 * CC, 1280, 1792, 1.f / (BB * NN));

    k_apply<<<16384, 256>>>(out);
}

// round 16
// speedup vs baseline: 1.7161x; 1.7161x over previous
#include <cuda_runtime.h>
#include <cstdint>

#define BB 16
#define NN 2048
#define CC 256
#define RR 128
#define KK 16

// ---------------- static device scratch ----------------
__device__ float g_xpre[BB * RR * NN];   // mlp1 pre-BN, channel-major
__device__ int   g_idx[BB * NN * KK];    // top-16 neighbor indices
__device__ float g_y[BB * NN * RR];      // fc(relu(bn1(xpre))), point-major
__device__ float g_x2c[BB * RR * NN];    // group-max output, channel-major
__device__ float g_mean[BB * RR * NN];   // laplacian neighbor-mean, channel-major
__device__ float g_t[BB * RR * NN];      // lu output pre-BN, channel-major
__device__ float g_y2[BB * CC * NN];     // mlp2 pre-BN, channel-major
__device__ float g_y3[BB * 2 * CC * NN]; // mlp3 pre-BN, channel-major
__device__ int   g_cnt[BB * NN];         // gather histogram for BNg
__device__ float g_stat[2304];           // per-BN sums / sumsqs
__device__ float g_aff[2304];            // per-BN scale / shift

__device__ __forceinline__ float tf32r(float x) {
    float o;
    asm("cvt.rna.tf32.f32 %0, %1;" : "=f"(o) : "f"(x));
    return o;
}

// ---------------- zero accumulators ----------------
__global__ void k_zero() {
    int i = blockIdx.x * 256 + threadIdx.x;
    if (i < BB * NN) g_cnt[i] = 0;
    if (i < 2304)    g_stat[i] = 0.f;
}

// ---------------- kNN top-16 on 2D coords (exact fp32, XLA association) ----------------
__global__ void k_knn(const float* __restrict__ xyz) {
    __shared__ float sx[NN];
    __shared__ float sy[NN];
    __shared__ float sxx[NN];
    int b = blockIdx.y;
    const float* px = xyz + (size_t)b * 3 * NN;
    for (int i = threadIdx.x; i < NN; i += 256) {
        float xv = px[i], yv = px[NN + i];
        sx[i] = xv; sy[i] = yv;
        sxx[i] = __fadd_rn(__fmul_rn(xv, xv), __fmul_rn(yv, yv));
    }
    __syncthreads();
    int n = blockIdx.x * 256 + threadIdx.x;
    float qx = sx[n], qy = sy[n], qxx = sxx[n];
    float bd[KK];
    int   bi[KK];
#pragma unroll
    for (int j = 0; j < KK; j++) { bd[j] = 3.4e38f; bi[j] = 0; }
    for (int m = 0; m < NN; m++) {
        float inner = __fmaf_rn(qy, sy[m], __fmul_rn(qx, sx[m]));
        float d = __fadd_rn(__fsub_rn(qxx, 2.f * inner), sxx[m]);
        if (d < bd[KK - 1]) {
            bd[KK - 1] = d; bi[KK - 1] = m;
#pragma unroll
            for (int j = KK - 1; j >= 1; j--) {
                if (bd[j] < bd[j - 1]) {
                    float td = bd[j]; bd[j] = bd[j - 1]; bd[j - 1] = td;
                    int   ti = bi[j]; bi[j] = bi[j - 1]; bi[j - 1] = ti;
                }
            }
        }
    }
    int* op = g_idx + ((size_t)b * NN + n) * KK;
#pragma unroll
    for (int j = 0; j < KK; j++) op[j] = bi[j];
}

// ---------------- histogram of first-8 neighbor indices ----------------
__global__ void k_cnt() {
    int b = blockIdx.x;
    for (int row = threadIdx.x; row < NN; row += blockDim.x) {
        const int* p = g_idx + ((size_t)b * NN + row) * KK;
#pragma unroll
        for (int j = 0; j < 8; j++) atomicAdd(&g_cnt[b * NN + p[j]], 1);
    }
}

// ---------------- pipelined tf32 mma GEMM: out = W @ f(in) + bias (channel-major) ----
// MODE 0: v = raw. MODE 2: v = relu(raw*sc+sh) + add. MODE 3: v = raw - add.
// Tile 128x128, 8 warps (4M x 2N). Permuted smem [row][(k&3)*8+(k>>2)], stride 34,
// LDS.64 fragment loads. Register prefetch of next K-chunk hides global latency.
template <int MODE>
__global__ void __launch_bounds__(256)
k_tmma(const float* __restrict__ W, const float* __restrict__ in,
       const float* __restrict__ bias,
       const float* __restrict__ scale, const float* __restrict__ shift,
       const float* __restrict__ add,
       float* __restrict__ out, int M, int Kd, int offS) {
    __shared__ __align__(16) float A2[128 * 34];
    __shared__ __align__(16) float B2[128 * 34];
    __shared__ float ssm[CC], shm[CC];
    int tid = threadIdx.x, wid = tid >> 5, lane = tid & 31;
    int gid = lane >> 2, tig = lane & 3;
    int b = blockIdx.z, n0 = blockIdx.x * 128, m0 = blockIdx.y * 128;
    int mw = wid >> 1, nw = wid & 1;
    const float* inb = in + (size_t)b * Kd * NN;
    const float* addb = (MODE >= 2) ? add + (size_t)b * Kd * NN : in;
    if (MODE == 2)
        for (int i = tid; i < Kd; i += 256) { ssm[i] = scale[i]; shm[i] = shift[i]; }

    float c[2][8][4];
#pragma unroll
    for (int i = 0; i < 2; i++)
#pragma unroll
        for (int j = 0; j < 8; j++)
#pragma unroll
            for (int q = 0; q < 4; q++) c[i][j][q] = 0.f;

    float ra[16], rb[16], rc[16];
    int nch = Kd >> 5;

    auto prefetch = [&](int ch) {
#pragma unroll
        for (int p = 0; p < 16; p++) {
            int e = tid + p * 256;
            int m = e >> 5, k = e & 31;
            ra[p] = W[(size_t)(m0 + m) * Kd + ch * 32 + k];
        }
#pragma unroll
        for (int p = 0; p < 16; p++) {
            int e = tid + p * 256;
            int n = e & 127, k = e >> 7;
            rb[p] = inb[(size_t)(ch * 32 + k) * NN + n0 + n];
            if (MODE >= 2) rc[p] = addb[(size_t)(ch * 32 + k) * NN + n0 + n];
        }
    };
    auto stor = [&](int ch) {
#pragma unroll
        for (int p = 0; p < 16; p++) {
            int e = tid + p * 256;
            int m = e >> 5, k = e & 31;
            A2[m * 34 + (k & 3) * 8 + (k >> 2)] = tf32r(ra[p]);
        }
#pragma unroll
        for (int p = 0; p < 16; p++) {
            int e = tid + p * 256;
            int n = e & 127, k = e >> 7;
            float v = rb[p];
            if (MODE == 2) v = fmaxf(fmaf(v, ssm[ch * 32 + k], shm[ch * 32 + k]), 0.f) + rc[p];
            if (MODE == 3) v = v - rc[p];
            B2[n * 34 + (k & 3) * 8 + (k >> 2)] = tf32r(v);
        }
    };

    prefetch(0);
    __syncthreads();
    stor(0);
    __syncthreads();
    for (int ch = 0; ch < nch; ch++) {
        if (ch + 1 < nch) prefetch(ch + 1);
#pragma unroll
        for (int ks = 0; ks < 4; ks++) {
            float2 af[2][2];
#pragma unroll
            for (int i = 0; i < 2; i++)
#pragma unroll
                for (int h = 0; h < 2; h++) {
                    int r = mw * 32 + i * 16 + h * 8 + gid;
                    af[i][h] = *reinterpret_cast<const float2*>(&A2[r * 34 + tig * 8 + 2 * ks]);
                }
#pragma unroll
            for (int j2 = 0; j2 < 8; j2++) {
                int n = nw * 64 + j2 * 8 + gid;
                float2 bf = *reinterpret_cast<const float2*>(&B2[n * 34 + tig * 8 + 2 * ks]);
#pragma unroll
                for (int i = 0; i < 2; i++) {
                    asm volatile(
                        "mma.sync.aligned.m16n8k8.row.col.f32.tf32.tf32.f32 "
                        "{%0,%1,%2,%3}, {%4,%5,%6,%7}, {%8,%9}, {%0,%1,%2,%3};"
                        : "+f"(c[i][j2][0]), "+f"(c[i][j2][1]),
                          "+f"(c[i][j2][2]), "+f"(c[i][j2][3])
                        : "r"(__float_as_uint(af[i][0].x)), "r"(__float_as_uint(af[i][1].x)),
                          "r"(__float_as_uint(af[i][0].y)), "r"(__float_as_uint(af[i][1].y)),
                          "r"(__float_as_uint(bf.x)), "r"(__float_as_uint(bf.y)));
                }
            }
        }
        if (ch + 1 < nch) {
            __syncthreads();
            stor(ch + 1);
            __syncthreads();
        }
    }

    // epilogue: bias, fused BN stats, float2 stores
    float sA[2][2] = {{0.f, 0.f}, {0.f, 0.f}};
    float qA[2][2] = {{0.f, 0.f}, {0.f, 0.f}};
#pragma unroll
    for (int i = 0; i < 2; i++) {
#pragma unroll
        for (int h = 0; h < 2; h++) {
            int row = m0 + mw * 32 + i * 16 + gid + h * 8;
            float bv = bias[row];
            float* orow = out + ((size_t)b * M + row) * NN + n0 + nw * 64;
#pragma unroll
            for (int j = 0; j < 8; j++) {
                float v0 = c[i][j][h * 2] + bv;
                float v1 = c[i][j][h * 2 + 1] + bv;
                sA[i][h] += v0 + v1;
                qA[i][h] += v0 * v0 + v1 * v1;
                *reinterpret_cast<float2*>(&orow[j * 8 + tig * 2]) = make_float2(v0, v1);
            }
        }
    }
    if (offS >= 0) {
#pragma unroll
        for (int i = 0; i < 2; i++)
#pragma unroll
            for (int h = 0; h < 2; h++) {
                float s = sA[i][h], q = qA[i][h];
                s += __shfl_xor_sync(0xffffffffu, s, 1);
                q += __shfl_xor_sync(0xffffffffu, q, 1);
                s += __shfl_xor_sync(0xffffffffu, s, 2);
                q += __shfl_xor_sync(0xffffffffu, q, 2);
                if (tig == 0) {
                    int row = m0 + mw * 32 + i * 16 + gid + h * 8;
                    atomicAdd(&g_stat[offS + row], s);
                    atomicAdd(&g_stat[offS + M + row], q);
                }
            }
    }
}

// ---------------- SIMT GEMM for fc (point-major out, fused weighted BNg stats) ----
__global__ void k_gemm_fc(const float* __restrict__ W, const float* __restrict__ in,
                          const float* __restrict__ bias,
                          const float* __restrict__ scale, const float* __restrict__ shift,
                          float* __restrict__ out) {
    const int M = RR, Kd = RR;
    __shared__ __align__(16) float Ws[16][68];
    __shared__ __align__(16) float Xs[16][68];
    int b = blockIdx.z;
    int n0 = blockIdx.x * 64, m0 = blockIdx.y * 64;
    int tid = threadIdx.x;
    int tx = tid & 15, ty = tid >> 4;
    const float* inb = in + (size_t)b * Kd * NN;
    float acc[4][4];
#pragma unroll
    for (int i = 0; i < 4; i++)
#pragma unroll
        for (int j = 0; j < 4; j++) acc[i][j] = 0.f;

    for (int k0 = 0; k0 < Kd; k0 += 16) {
        int kw = tid & 15, mw = tid >> 4;
#pragma unroll
        for (int p = 0; p < 4; p++)
            Ws[kw][mw + p * 16] = tf32r(W[(size_t)(m0 + mw + p * 16) * Kd + k0 + kw]);
        int nn2 = tid & 63, kk = tid >> 6;
#pragma unroll
        for (int p = 0; p < 4; p++) {
            int kg = k0 + kk + p * 4;
            float v = inb[(size_t)kg * NN + n0 + nn2];
            v = fmaxf(fmaf(v, scale[kg], shift[kg]), 0.f);
            Xs[kk + p * 4][nn2] = tf32r(v);
        }
        __syncthreads();
#pragma unroll
        for (int kk2 = 0; kk2 < 16; kk2++) {
            float4 xv = *reinterpret_cast<const float4*>(&Xs[kk2][tx * 4]);
            float4 wv = *reinterpret_cast<const float4*>(&Ws[kk2][ty * 4]);
            float xa[4] = {xv.x, xv.y, xv.z, xv.w};
            float wa[4] = {wv.x, wv.y, wv.z, wv.w};
#pragma unroll
            for (int i = 0; i < 4; i++)
#pragma unroll
                for (int j = 0; j < 4; j++)
                    acc[i][j] = fmaf(wa[i], xa[j], acc[i][j]);
        }
        __syncthreads();
    }
    float sW[4] = {0.f, 0.f, 0.f, 0.f}, qW[4] = {0.f, 0.f, 0.f, 0.f};
    int m = m0 + ty * 4;
#pragma unroll
    for (int j = 0; j < 4; j++) {
        int n = n0 + tx * 4 + j;
        float cw = (float)g_cnt[b * NN + n];
        float o0 = acc[0][j] + bias[m],     o1 = acc[1][j] + bias[m + 1];
        float o2 = acc[2][j] + bias[m + 2], o3 = acc[3][j] + bias[m + 3];
        *reinterpret_cast<float4*>(&out[((size_t)b * NN + n) * M + m]) =
            make_float4(o0, o1, o2, o3);
        sW[0] += cw * o0; qW[0] += cw * o0 * o0;
        sW[1] += cw * o1; qW[1] += cw * o1 * o1;
        sW[2] += cw * o2; qW[2] += cw * o2 * o2;
        sW[3] += cw * o3; qW[3] += cw * o3 * o3;
    }
#pragma unroll
    for (int i = 0; i < 4; i++) {
        float s = sW[i], q = qW[i];
#pragma unroll
        for (int off = 1; off < 16; off <<= 1) {
            s += __shfl_xor_sync(0xffffffffu, s, off);
            q += __shfl_xor_sync(0xffffffffu, q, off);
        }
        if (tx == 0) {
            atomicAdd(&g_stat[256 + m + i], s);
            atomicAdd(&g_stat[384 + m + i], q);
        }
    }
}

// ---------------- finalize BN affine ----------------
__global__ void k_fin(const float* __restrict__ gamma, const float* __restrict__ beta,
                      int M, int offS, int offQ, float invcnt) {
    int m = blockIdx.x * 256 + threadIdx.x;
    if (m >= M) return;
    float mu = g_stat[offS + m] * invcnt;
    float var = g_stat[offQ + m] * invcnt - mu * mu;
    float sc = gamma[m] * rsqrtf(var + 1e-5f);
    g_aff[offS + m] = sc;
    g_aff[offQ + m] = beta[m] - mu * sc;
}

// ---------------- group max, 32 n2 per block, coalesced in and out ----------------
__global__ void __launch_bounds__(256) k_gmax2() {
    __shared__ int sj[32 * 8];
    __shared__ float ob[128 * 33];
    int b = blockIdx.y, nc = blockIdx.x, tid = threadIdx.x;
    {
        int i = tid >> 3, kg = tid & 7;
        int n2 = nc * 32 + i;
        sj[tid] = g_idx[((size_t)b * NN + kg * 256 + (n2 >> 3)) * KK + (n2 & 7)];
    }
    __syncthreads();
    int r = tid & 127, ih = tid >> 7;
    float sc = g_aff[256 + r], sh = g_aff[384 + r];
    for (int t = 0; t < 16; t++) {
        int i = ih * 16 + t;
        float u = 0.f;
#pragma unroll
        for (int kg = 0; kg < 8; kg++) {
            float v = g_y[((size_t)b * NN + sj[i * 8 + kg]) * RR + r];
            u = fmaxf(u, fmaxf(fmaf(v, sc, sh), 0.f));
        }
        ob[r * 33 + i] = u;
    }
    __syncthreads();
    for (int q = 0; q < 16; q++) {
        int e = tid + q * 256;
        int row = e >> 5, col = e & 31;
        g_x2c[((size_t)b * RR + row) * NN + nc * 32 + col] = ob[row * 33 + col];
    }
}

// ---------------- laplacian neighbor-mean, coalesced channel-major output ----------
// Block (nc, b): covers n2 in [nc*32, nc*32+32). p = n2>>4 in {2nc, 2nc+1} (2 smem rows).
// s = n2&15 = t; idx read straight from L2 (coalesced, hot).
__global__ void __launch_bounds__(256) k_lap3() {
    __shared__ float xr2[2][2048];
    __shared__ float ob[128 * 33];
    int b = blockIdx.y, nc = blockIdx.x, tid = threadIdx.x;
    int r2 = tid & 127, ih = tid >> 7, u = r2 >> 4, j = r2 & 15;
    {
        const float4* src = reinterpret_cast<const float4*>(
            g_x2c + ((size_t)b * RR + nc * 2) * NN);
        float4* dst = reinterpret_cast<float4*>(&xr2[0][0]);
#pragma unroll
        for (int q = 0; q < 4; q++) dst[tid + q * 256] = src[tid + q * 256];
    }
    __syncthreads();
    for (int t = 0; t < 16; t++) {
        const int* ib = g_idx + ((size_t)b * NN + t * 128) * KK;
        float acc = 0.f;
#pragma unroll
        for (int k2 = 0; k2 < 16; k2++)
            acc += xr2[ih][ib[(k2 * 8 + u) * 16 + j]];
        ob[r2 * 33 + ih * 16 + t] = acc * (1.f / 16.f);
    }
    __syncthreads();
    for (int q = 0; q < 16; q++) {
        int e = tid + q * 256;
        int row = e >> 5, col = e & 31;
        g_mean[((size_t)b * RR + row) * NN + nc * 32 + col] = ob[row * 33 + col];
    }
}

// ---------------- final BN3 apply (float4) ----------------
__global__ void k_apply(float* __restrict__ out) {
    int i4 = blockIdx.x * 256 + threadIdx.x;
    int c = (i4 >> 9) & 511;
    float sc = g_aff[1280 + c], sh = g_aff[1792 + c];
    float4 v = reinterpret_cast<const float4*>(g_y3)[i4];
    float4 o;
    o.x = fmaxf(fmaf(v.x, sc, sh), 0.f);
    o.y = fmaxf(fmaf(v.y, sc, sh), 0.f);
    o.z = fmaxf(fmaf(v.z, sc, sh), 0.f);
    o.w = fmaxf(fmaf(v.w, sc, sh), 0.f);
    reinterpret_cast<float4*>(out)[i4] = o;
}

extern "C" void kernel_launch(void* const* d_in, const int* in_sizes, int n_in,
                              void* d_out, int out_size) {
    const float* xyz   = (const float*)d_in[0];
    const float* feat  = (const float*)d_in[1];
    const float* w1    = (const float*)d_in[2];
    const float* b1    = (const float*)d_in[3];
    const float* bn1_g = (const float*)d_in[4];
    const float* bn1_b = (const float*)d_in[5];
    const float* fc_w  = (const float*)d_in[6];
    const float* fc_b  = (const float*)d_in[7];
    const float* bng_g = (const float*)d_in[8];
    const float* bng_b = (const float*)d_in[9];
    const float* lu_w  = (const float*)d_in[10];
    const float* lu_b  = (const float*)d_in[11];
    const float* bnl_g = (const float*)d_in[12];
    const float* bnl_b = (const float*)d_in[13];
    const float* w2    = (const float*)d_in[14];
    const float* b2    = (const float*)d_in[15];
    const float* bn2_g = (const float*)d_in[16];
    const float* bn2_b = (const float*)d_in[17];
    const float* w3    = (const float*)d_in[18];
    const float* b3    = (const float*)d_in[19];
    const float* bn3_g = (const float*)d_in[20];
    const float* bn3_b = (const float*)d_in[21];
    float* out = (float*)d_out;

    float *xpre, *y, *x2c, *meanp, *t, *y2, *y3, *aff;
    cudaGetSymbolAddress((void**)&xpre,  g_xpre);
    cudaGetSymbolAddress((void**)&y,     g_y);
    cudaGetSymbolAddress((void**)&x2c,   g_x2c);
    cudaGetSymbolAddress((void**)&meanp, g_mean);
    cudaGetSymbolAddress((void**)&t,     g_t);
    cudaGetSymbolAddress((void**)&y2,    g_y2);
    cudaGetSymbolAddress((void**)&y3,    g_y3);
    cudaGetSymbolAddress((void**)&aff,   g_aff);

    k_zero<<<128, 256>>>();
    k_knn<<<dim3(8, BB), 256>>>(xyz);
    k_cnt<<<BB, 512>>>();

    // mlp1: xpre = w1 @ feat + b1   (stats -> 0/128)
    k_tmma<0><<<dim3(16, 1, BB), 256>>>(w1, feat, b1, nullptr, nullptr, nullptr, xpre, RR, CC, 0);
    k_fin<<<1, 256>>>(bn1_g, bn1_b, RR, 0, 128, 1.f / (BB * NN));

    // fc pre-gather (SIMT, point-major out, fused weighted BNg stats -> 256/384)
    k_gemm_fc<<<dim3(32, 2, BB), 256>>>(fc_w, xpre, fc_b, aff, aff + 128, y);
    k_fin<<<1, 256>>>(bng_g, bng_b, RR, 256, 384, 1.f / 262144.f);

    k_gmax2<<<dim3(64, BB), 256>>>();
    k_lap3<<<dim3(64, BB), 256>>>();

    // lu: t = lu_w @ (x2c - mean) + lu_b   (MODE3, stats -> 512/640)
    k_tmma<3><<<dim3(16, 1, BB), 256>>>(lu_w, x2c, lu_b, nullptr, nullptr, meanp, t, RR, RR, 512);
    k_fin<<<1, 256>>>(bnl_g, bnl_b, RR, 512, 640, 1.f / (BB * NN));

    // mlp2: y2 = w2 @ (relu(bnl(t)) + x2c) + b2   (stats -> 768/1024)
    k_tmma<2><<<dim3(16, 2, BB), 256>>>(w2, t, b2, aff + 512, aff + 640, x2c, y2, CC, RR, 768);
    k_fin<<<1, 256>>>(bn2_g, bn2_b, CC, 768, 1024, 1.f / (BB * NN));

    // mlp3: y3 = w3 @ (relu(bn2(y2)) + feat) + b3   (stats -> 1280/1792)
    k_tmma<2><<<dim3(16, 4, BB), 256>>>(w3, y2, b3, aff + 768, aff + 1024, feat, y3, 2 * CC, CC, 1280);
    k_fin<<<2, 256>>>(bn3_g, bn3_b, 2 * CC, 1280, 1792, 1.f / (BB * NN));

    k_apply<<<16384, 256>>>(out);
}